// round 1
// baseline (speedup 1.0000x reference)
#include <cuda_runtime.h>
#include <cuda_bf16.h>
#include <math.h>

// Problem constants
#define B_   8
#define S_   4096
#define D_   512
#define P_   128
#define L_   4
#define DF_  2048
#define DH_  256
#define C_   2
#define BS_  (B_*S_)   // 32768 tokens

// -------- scratch (device globals; no allocation allowed) --------
__device__ float g_h[(size_t)BS_*D_];
__device__ float g_q[(size_t)BS_*D_];
__device__ float g_k[(size_t)BS_*D_];
__device__ float g_v[(size_t)BS_*D_];
__device__ float g_a[(size_t)BS_*D_];
__device__ float g_pq[(size_t)BS_*P_];
__device__ float g_pk[(size_t)BS_*P_];
__device__ float g_kv[(size_t)B_*P_*D_];
__device__ float g_ksum[B_*P_];
__device__ float g_z[BS_];
__device__ float g_m[(size_t)BS_*DF_];
__device__ float g_pool[B_*D_];
__device__ float g_h1[B_*DH_];

// -------- GEMM: C[M,N] = A[M,K] @ W[K,N] (+bias) with epilogues --------
#define BM 64
#define BN 64
#define BK 16

enum { EP_NONE = 0, EP_ELU1 = 1, EP_GELU = 2, EP_ZSCALE = 3 };

__device__ __forceinline__ float gelu_f(float x) {
    // JAX default gelu: tanh approximation
    float x3 = x * x * x;
    float t  = tanhf(0.7978845608028654f * (x + 0.044715f * x3));
    return 0.5f * x * (1.0f + t);
}

template <int EPI>
__global__ void __launch_bounds__(256) gemm_nn_k(
    const float* __restrict__ A, const float* __restrict__ W,
    const float* __restrict__ bias, float* __restrict__ Cp,
    const float* __restrict__ zr,
    int M, int N, int K, long sA, long sW, long sC)
{
    __shared__ __align__(16) float As[BK][BM + 4];
    __shared__ __align__(16) float Bs[BK][BN + 4];

    int bz = blockIdx.z;
    A  += (long)bz * sA;
    W  += (long)bz * sW;
    Cp += (long)bz * sC;
    const float* zrow = (EPI == EP_ZSCALE) ? (zr + (long)bz * M) : nullptr;

    int m0 = blockIdx.y * BM;
    int n0 = blockIdx.x * BN;
    int tid = threadIdx.x;
    int tx = tid & 15, ty = tid >> 4;

    float acc[4][4] = {};

    for (int k0 = 0; k0 < K; k0 += BK) {
        // A tile: 64x16, As[c][r] (transposed into smem)
#pragma unroll
        for (int e = 0; e < 4; e++) {
            int idx = tid + e * 256;
            int r = idx >> 4, c = idx & 15;
            As[c][r] = A[(long)(m0 + r) * K + (k0 + c)];
        }
        // W tile: 16x64
#pragma unroll
        for (int e = 0; e < 4; e++) {
            int idx = tid + e * 256;
            int r = idx >> 6, c = idx & 63;
            Bs[r][c] = W[(long)(k0 + r) * N + (n0 + c)];
        }
        __syncthreads();
#pragma unroll
        for (int kk = 0; kk < BK; kk++) {
            float4 av = *reinterpret_cast<const float4*>(&As[kk][ty * 4]);
            float4 bv = *reinterpret_cast<const float4*>(&Bs[kk][tx * 4]);
            float a4[4] = {av.x, av.y, av.z, av.w};
            float b4[4] = {bv.x, bv.y, bv.z, bv.w};
#pragma unroll
            for (int i = 0; i < 4; i++)
#pragma unroll
                for (int j = 0; j < 4; j++)
                    acc[i][j] = fmaf(a4[i], b4[j], acc[i][j]);
        }
        __syncthreads();
    }

#pragma unroll
    for (int i = 0; i < 4; i++) {
        int m = m0 + ty * 4 + i;
        float zs = 0.f;
        if (EPI == EP_ZSCALE) zs = 1.0f / (zrow[m] + 1e-6f);
#pragma unroll
        for (int j = 0; j < 4; j++) {
            int n = n0 + tx * 4 + j;
            float v = acc[i][j];
            if (bias) v += bias[n];
            if (EPI == EP_ELU1)   v = (v > 0.f) ? (v + 1.0f) : expf(v);
            if (EPI == EP_GELU)   v = gelu_f(v);
            if (EPI == EP_ZSCALE) v *= zs;
            Cp[(long)m * N + n] = v;
        }
    }
}

// -------- GEMM TN: C[M,N] = sum_k A[k,M] * B[k,N] (batched; kv = pk^T @ v) --------
__global__ void __launch_bounds__(256) gemm_tn_k(
    const float* __restrict__ A, const float* __restrict__ Bp, float* __restrict__ Cp,
    int M, int N, int K, long sA, long sB, long sC)
{
    __shared__ __align__(16) float As[BK][BM + 4];
    __shared__ __align__(16) float Bs[BK][BN + 4];

    int bz = blockIdx.z;
    A  += (long)bz * sA;
    Bp += (long)bz * sB;
    Cp += (long)bz * sC;

    int m0 = blockIdx.y * BM;
    int n0 = blockIdx.x * BN;
    int tid = threadIdx.x;
    int tx = tid & 15, ty = tid >> 4;

    float acc[4][4] = {};

    for (int k0 = 0; k0 < K; k0 += BK) {
#pragma unroll
        for (int e = 0; e < 4; e++) {
            int idx = tid + e * 256;
            int r = idx >> 6, c = idx & 63;
            As[r][c] = A[(long)(k0 + r) * M + (m0 + c)];
            Bs[r][c] = Bp[(long)(k0 + r) * N + (n0 + c)];
        }
        __syncthreads();
#pragma unroll
        for (int kk = 0; kk < BK; kk++) {
            float4 av = *reinterpret_cast<const float4*>(&As[kk][ty * 4]);
            float4 bv = *reinterpret_cast<const float4*>(&Bs[kk][tx * 4]);
            float a4[4] = {av.x, av.y, av.z, av.w};
            float b4[4] = {bv.x, bv.y, bv.z, bv.w};
#pragma unroll
            for (int i = 0; i < 4; i++)
#pragma unroll
                for (int j = 0; j < 4; j++)
                    acc[i][j] = fmaf(a4[i], b4[j], acc[i][j]);
        }
        __syncthreads();
    }

#pragma unroll
    for (int i = 0; i < 4; i++) {
        int m = m0 + ty * 4 + i;
#pragma unroll
        for (int j = 0; j < 4; j++) {
            int n = n0 + tx * 4 + j;
            Cp[(long)m * N + n] = acc[i][j];
        }
    }
}

// -------- embedding + positional --------
__global__ void embed_k(const int* __restrict__ x, const float* __restrict__ emb,
                        const float* __restrict__ pos, float* __restrict__ h)
{
    long idx = (long)blockIdx.x * 256 + threadIdx.x;   // [0, BS_*D_)
    int  d   = (int)(idx & (D_ - 1));
    long tok = idx >> 9;                                // D_ = 512
    int  s   = (int)(tok & (S_ - 1));                   // S_ = 4096
    int  xv  = x[tok];
    h[idx] = emb[(long)xv * D_ + d] + pos[(long)s * D_ + d];
}

// -------- ksum[b,p] = sum_s pk[b,s,p] --------
__global__ void ksum_k(const float* __restrict__ pk, float* __restrict__ ks)
{
    int b = blockIdx.x;
    int tid = threadIdx.x;          // 1024
    int p = tid & 127;
    int sg = tid >> 7;              // 0..7
    const float* base = pk + (long)b * S_ * P_;
    float s = 0.f;
    for (int si = sg; si < S_; si += 8)
        s += base[(long)si * P_ + p];
    __shared__ float red[1024];
    red[tid] = s;
    __syncthreads();
    if (sg == 0) {
        float t = 0.f;
#pragma unroll
        for (int g = 0; g < 8; g++) t += red[g * 128 + p];
        ks[b * P_ + p] = t;
    }
}

// -------- z[b,s] = pq[b,s,:] . ksum[b,:] --------
__global__ void z_k(const float* __restrict__ pq, const float* __restrict__ ks,
                    float* __restrict__ z)
{
    int row  = blockIdx.x * 8 + (threadIdx.x >> 5);   // global token row
    int lane = threadIdx.x & 31;
    int b = row >> 12;                                 // /S_
    const float* pr = pq + (long)row * P_;
    const float* kk = ks + b * P_;
    float s = 0.f;
#pragma unroll
    for (int i = lane; i < P_; i += 32) s += pr[i] * kk[i];
#pragma unroll
    for (int o = 16; o; o >>= 1) s += __shfl_xor_sync(0xffffffffu, s, o);
    if (!lane) z[row] = s;
}

// -------- layernorm over D=512 (in-place safe) --------
__global__ void ln_k(const float* __restrict__ in, const float* __restrict__ g,
                     const float* __restrict__ bb, float* __restrict__ out)
{
    int row = blockIdx.x;
    int t = threadIdx.x;   // 256
    const float* x = in + (long)row * D_;
    float v0 = x[t], v1 = x[t + 256];

    float s = v0 + v1;
    __shared__ float red[8];
    __shared__ float red2[8];
#pragma unroll
    for (int o = 16; o; o >>= 1) s += __shfl_xor_sync(0xffffffffu, s, o);
    if ((t & 31) == 0) red[t >> 5] = s;
    __syncthreads();
    float tot = 0.f;
#pragma unroll
    for (int w = 0; w < 8; w++) tot += red[w];
    float mean = tot * (1.0f / 512.0f);

    float d0 = v0 - mean, d1 = v1 - mean;
    float q = d0 * d0 + d1 * d1;
#pragma unroll
    for (int o = 16; o; o >>= 1) q += __shfl_xor_sync(0xffffffffu, q, o);
    if ((t & 31) == 0) red2[t >> 5] = q;
    __syncthreads();
    float tq = 0.f;
#pragma unroll
    for (int w = 0; w < 8; w++) tq += red2[w];
    float inv = rsqrtf(tq * (1.0f / 512.0f) + 1e-5f);

    out[(long)row * D_ + t]       = d0 * inv * g[t] + bb[t];
    out[(long)row * D_ + t + 256] = d1 * inv * g[t + 256] + bb[t + 256];
}

// -------- mean pool over S --------
__global__ void pool_k(const float* __restrict__ h, float* __restrict__ pool)
{
    int b = blockIdx.x;
    int d = threadIdx.x;   // 512
    const float* base = h + (long)b * S_ * D_ + d;
    float s0 = 0.f, s1 = 0.f, s2 = 0.f, s3 = 0.f;
    for (int si = 0; si < S_; si += 4) {
        s0 += base[(long)(si + 0) * D_];
        s1 += base[(long)(si + 1) * D_];
        s2 += base[(long)(si + 2) * D_];
        s3 += base[(long)(si + 3) * D_];
    }
    pool[b * D_ + d] = (s0 + s1 + s2 + s3) * (1.0f / (float)S_);
}

// -------- head --------
__global__ void head1_k(const float* __restrict__ pool, const float* __restrict__ W,
                        const float* __restrict__ bias, float* __restrict__ h1)
{
    int b = blockIdx.x;
    int j = threadIdx.x;   // 256 = DH_
    const float* p = pool + b * D_;
    float s = bias[j];
    for (int d = 0; d < D_; d++) s += p[d] * W[d * DH_ + j];
    h1[b * DH_ + j] = fmaxf(s, 0.f);
}

__global__ void head2_k(const float* __restrict__ h1, const float* __restrict__ W,
                        const float* __restrict__ bias, float* __restrict__ out)
{
    int i = threadIdx.x;   // 16 = B_*C_
    int b = i / C_, c = i % C_;
    float s = bias[c];
    for (int d = 0; d < DH_; d++) s += h1[b * DH_ + d] * W[d * C_ + c];
    out[i] = s;
}

// -------- host orchestration --------
static float* sym_addr_f(const void* sym) {
    void* p = nullptr;
    cudaGetSymbolAddress(&p, sym);
    return (float*)p;
}

extern "C" void kernel_launch(void* const* d_in, const int* in_sizes, int n_in,
                              void* d_out, int out_size)
{
    const int*   x    = (const int*)d_in[0];
    const float* emb  = (const float*)d_in[1];
    const float* pos  = (const float*)d_in[2];
    const float* Wq   = (const float*)d_in[3];
    const float* bq   = (const float*)d_in[4];
    const float* Wk   = (const float*)d_in[5];
    const float* bk   = (const float*)d_in[6];
    const float* Wv   = (const float*)d_in[7];
    const float* bv   = (const float*)d_in[8];
    const float* Wf   = (const float*)d_in[9];
    const float* bf   = (const float*)d_in[10];
    const float* Wo   = (const float*)d_in[11];
    const float* bo   = (const float*)d_in[12];
    const float* lng  = (const float*)d_in[13];
    const float* lnb  = (const float*)d_in[14];
    const float* W1   = (const float*)d_in[15];
    const float* b1   = (const float*)d_in[16];
    const float* W2   = (const float*)d_in[17];
    const float* b2   = (const float*)d_in[18];
    const float* Wh1  = (const float*)d_in[19];
    const float* bh1  = (const float*)d_in[20];
    const float* Wh2  = (const float*)d_in[21];
    const float* bh2  = (const float*)d_in[22];
    float* out = (float*)d_out;

    float* h    = sym_addr_f(g_h);
    float* q    = sym_addr_f(g_q);
    float* k    = sym_addr_f(g_k);
    float* v    = sym_addr_f(g_v);
    float* a    = sym_addr_f(g_a);
    float* pq   = sym_addr_f(g_pq);
    float* pk   = sym_addr_f(g_pk);
    float* kv   = sym_addr_f(g_kv);
    float* ksum = sym_addr_f(g_ksum);
    float* z    = sym_addr_f(g_z);
    float* m    = sym_addr_f(g_m);
    float* pool = sym_addr_f(g_pool);
    float* h1   = sym_addr_f(g_h1);

    dim3 thr(256);

    embed_k<<<(BS_ * D_) / 256, 256>>>(x, emb, pos, h);

    for (int l = 0; l < L_; l++) {
        const float* wq = Wq + (long)l * D_ * D_;
        const float* wk = Wk + (long)l * D_ * D_;
        const float* wv = Wv + (long)l * D_ * D_;
        const float* wf = Wf + (long)l * D_ * P_;
        const float* wo = Wo + (long)l * D_ * D_;
        const float* w1 = W1 + (long)l * D_ * DF_;
        const float* w2 = W2 + (long)l * DF_ * D_;

        dim3 gQKV(D_ / BN, BS_ / BM, 1);
        gemm_nn_k<EP_NONE><<<gQKV, thr>>>(h, wq, bq + l * D_, q, nullptr, BS_, D_, D_, 0, 0, 0);
        gemm_nn_k<EP_NONE><<<gQKV, thr>>>(h, wk, bk + l * D_, k, nullptr, BS_, D_, D_, 0, 0, 0);
        gemm_nn_k<EP_NONE><<<gQKV, thr>>>(h, wv, bv + l * D_, v, nullptr, BS_, D_, D_, 0, 0, 0);

        dim3 gF(P_ / BN, BS_ / BM, 1);
        gemm_nn_k<EP_ELU1><<<gF, thr>>>(q, wf, bf + l * P_, pq, nullptr, BS_, P_, D_, 0, 0, 0);
        gemm_nn_k<EP_ELU1><<<gF, thr>>>(k, wf, bf + l * P_, pk, nullptr, BS_, P_, D_, 0, 0, 0);

        ksum_k<<<B_, 1024>>>(pk, ksum);

        // kv[b] = pk[b]^T @ v[b]  : [P_ x D_], K = S_
        dim3 gKV(D_ / BN, P_ / BM, B_);
        gemm_tn_k<<<gKV, thr>>>(pk, v, kv, P_, D_, S_,
                                (long)S_ * P_, (long)S_ * D_, (long)P_ * D_);

        z_k<<<BS_ / 8, 256>>>(pq, ksum, z);

        // attn_raw[b] = (pq[b] @ kv[b]) / (z + eps)  -> reuse q buffer
        dim3 gAV(D_ / BN, S_ / BM, B_);
        gemm_nn_k<EP_ZSCALE><<<gAV, thr>>>(pq, kv, nullptr, q, z, S_, D_, P_,
                                           (long)S_ * P_, (long)P_ * D_, (long)S_ * D_);

        gemm_nn_k<EP_NONE><<<gQKV, thr>>>(q, wo, bo + l * D_, a, nullptr, BS_, D_, D_, 0, 0, 0);

        ln_k<<<BS_, 256>>>(a, lng + l * D_, lnb + l * D_, a);

        dim3 gW1(DF_ / BN, BS_ / BM, 1);
        gemm_nn_k<EP_GELU><<<gW1, thr>>>(a, w1, b1 + l * DF_, m, nullptr, BS_, DF_, D_, 0, 0, 0);

        dim3 gW2(D_ / BN, BS_ / BM, 1);
        gemm_nn_k<EP_NONE><<<gW2, thr>>>(m, w2, b2 + l * D_, h, nullptr, BS_, D_, DF_, 0, 0, 0);
    }

    pool_k<<<B_, 512>>>(h, pool);
    head1_k<<<B_, DH_>>>(pool, Wh1, bh1, h1);
    head2_k<<<1, B_ * C_>>>(h1, Wh2, bh2, out);
}

// round 3
// speedup vs baseline: 2.3663x; 2.3663x over previous
#include <cuda_runtime.h>
#include <cuda_bf16.h>
#include <math.h>
#include <stdint.h>

// Problem constants
#define B_   8
#define S_   4096
#define D_   512
#define P_   128
#define L_   4
#define DF_  2048
#define DH_  256
#define C_   2
#define BS_  (B_*S_)   // 32768 tokens

// -------- scratch (device globals; no allocation allowed) --------
__device__ float g_h[(size_t)BS_*D_];
__device__ float g_q[(size_t)BS_*D_];
__device__ float g_k[(size_t)BS_*D_];
__device__ float g_v[(size_t)BS_*D_];
__device__ float g_a[(size_t)BS_*D_];
__device__ float g_pq[(size_t)BS_*P_];
__device__ float g_pk[(size_t)BS_*P_];
__device__ float g_kv[(size_t)B_*P_*D_];
__device__ float g_ksum[B_*P_];
__device__ float g_z[BS_];
__device__ float g_m[(size_t)BS_*DF_];
__device__ float g_pool[B_*D_];
__device__ float g_h1[B_*DH_];

// bf16 split buffers
__device__ __nv_bfloat16 g_ah[(size_t)BS_*DF_];   // activation hi
__device__ __nv_bfloat16 g_al[(size_t)BS_*DF_];   // activation lo
__device__ __nv_bfloat16 g_wth[(size_t)DF_*D_];   // transposed weight hi
__device__ __nv_bfloat16 g_wtl[(size_t)DF_*D_];   // transposed weight lo

enum { EP_NONE = 0, EP_ELU1 = 1, EP_GELU = 2 };

__device__ __forceinline__ float gelu_f(float x) {
    float x3 = x * x * x;
    float t  = tanhf(0.7978845608028654f * (x + 0.044715f * x3));
    return 0.5f * x * (1.0f + t);
}

__device__ __forceinline__ float epi_apply(float v, int EPI) {
    if (EPI == EP_ELU1) v = (v > 0.f) ? (v + 1.0f) : expf(v);
    if (EPI == EP_GELU) v = gelu_f(v);
    return v;
}

// ================= mma.sync bf16 GEMM (split precision, bf16x3) =================
// C[M,N] = A[M,K] @ Bt[N,K]^T (+bias, epilogue)
// A as hi/lo bf16 [M,K] K-major, Bt as hi/lo bf16 [N,K] K-major.
// CTA tile 128x128, 8 warps (2 M x 4 N), warp tile 64x32, K-chunk 32,
// double-buffered smem via cp.async. Padded smem stride 40 bf16 (80B).

#define SPAD   40                 // smem row stride in bf16 elems
#define TILE_B (128 * SPAD * 2)   // 10240 bytes per operand tile
#define STAGE_B (4 * TILE_B)      // Ah, Al, Bh, Bl
#define MMA_SMEM (2 * STAGE_B)    // 81920

__device__ __forceinline__ uint32_t smem_u32(const void* p) {
    uint32_t a;
    asm("{ .reg .u64 t; cvta.to.shared.u64 t, %1; cvt.u32.u64 %0, t; }" : "=r"(a) : "l"(p));
    return a;
}

#define CP_ASYNC16(dst, src) \
    asm volatile("cp.async.cg.shared.global [%0], [%1], 16;" :: "r"(dst), "l"(src) : "memory")
#define CP_COMMIT() asm volatile("cp.async.commit_group;" ::: "memory")
#define CP_WAIT1()  asm volatile("cp.async.wait_group 1;" ::: "memory")
#define CP_WAIT0()  asm volatile("cp.async.wait_group 0;" ::: "memory")

__device__ __forceinline__ void mma_bf16(float* c, uint32_t a0, uint32_t a1, uint32_t a2,
                                         uint32_t a3, uint32_t b0, uint32_t b1) {
    asm volatile(
        "mma.sync.aligned.m16n8k16.row.col.f32.bf16.bf16.f32 "
        "{%0,%1,%2,%3}, {%4,%5,%6,%7}, {%8,%9}, {%0,%1,%2,%3};"
        : "+f"(c[0]), "+f"(c[1]), "+f"(c[2]), "+f"(c[3])
        : "r"(a0), "r"(a1), "r"(a2), "r"(a3), "r"(b0), "r"(b1));
}

template <int EPI>
__global__ void __launch_bounds__(256, 2) gemm_mma(
    const __nv_bfloat16* __restrict__ Ah, const __nv_bfloat16* __restrict__ Al,
    const __nv_bfloat16* __restrict__ Bh, const __nv_bfloat16* __restrict__ Bl,
    const float* __restrict__ bias, float* __restrict__ C,
    int M, int N, int K)
{
    extern __shared__ __align__(1024) char smem[];
    const uint32_t sb = smem_u32(smem);

    const int tid  = threadIdx.x;
    const int wid  = tid >> 5;
    const int lane = tid & 31;
    const int wm   = wid & 1;       // 0..1  (64-row half)
    const int wn   = wid >> 1;      // 0..3  (32-col quarter)
    const int n0   = blockIdx.x * 128;
    const int m0   = blockIdx.y * 128;

    const __nv_bfloat16* gsrc[4] = {
        Ah + (size_t)m0 * K, Al + (size_t)m0 * K,
        Bh + (size_t)n0 * K, Bl + (size_t)n0 * K
    };

    // per-thread load assignments: 2 chunks of 16B per operand tile
    const int r0 = tid >> 2, p0 = tid & 3;              // chunk tid
    const int r1 = (tid + 256) >> 2, p1 = tid & 3;      // chunk tid+256

    const int nch = K >> 5;   // K/32
    float acc[4][4][4] = {};

    // prologue: load chunk 0 into stage 0
    {
        const int kc = 0;
#pragma unroll
        for (int t = 0; t < 4; t++) {
            const __nv_bfloat16* src = gsrc[t] + kc;
            uint32_t tb = sb + t * TILE_B;
            CP_ASYNC16(tb + (uint32_t)(r0 * (SPAD * 2) + p0 * 16),
                       (const void*)(src + (size_t)r0 * K + p0 * 8));
            CP_ASYNC16(tb + (uint32_t)(r1 * (SPAD * 2) + p1 * 16),
                       (const void*)(src + (size_t)r1 * K + p1 * 8));
        }
        CP_COMMIT();
    }

    for (int c = 0; c < nch; c++) {
        if (c + 1 < nch) {
            const int kc = (c + 1) << 5;
            const uint32_t stb = sb + ((c + 1) & 1) * STAGE_B;
#pragma unroll
            for (int t = 0; t < 4; t++) {
                const __nv_bfloat16* src = gsrc[t] + kc;
                uint32_t tb = stb + t * TILE_B;
                CP_ASYNC16(tb + (uint32_t)(r0 * (SPAD * 2) + p0 * 16),
                           (const void*)(src + (size_t)r0 * K + p0 * 8));
                CP_ASYNC16(tb + (uint32_t)(r1 * (SPAD * 2) + p1 * 16),
                           (const void*)(src + (size_t)r1 * K + p1 * 8));
            }
            CP_COMMIT();
            CP_WAIT1();
        } else {
            CP_WAIT0();
        }
        __syncthreads();

        const uint32_t stb = sb + (c & 1) * STAGE_B;
        const char* As[2] = { smem + (stb - sb) + 0 * TILE_B,   // Ah
                              smem + (stb - sb) + 1 * TILE_B }; // Al
        const char* Bs[2] = { smem + (stb - sb) + 2 * TILE_B,   // Bh
                              smem + (stb - sb) + 3 * TILE_B }; // Bl

        const int arow = wm * 64 + (lane >> 2);      // +mt*16 (+8)
        const int brow = wn * 32 + (lane >> 2);      // +nt*8
        const int kcol = (lane & 3) * 2;

#pragma unroll
        for (int ks = 0; ks < 2; ks++) {
            const int kb = ks * 16 + kcol;           // bf16 col within chunk
            // three passes: (Ah,Bh), (Ah,Bl), (Al,Bh)
#pragma unroll
            for (int pass = 0; pass < 3; pass++) {
                const char* Ap = As[pass == 2 ? 1 : 0];
                const char* Bp = Bs[pass == 1 ? 1 : 0];
                uint32_t af[4][4];
#pragma unroll
                for (int mt = 0; mt < 4; mt++) {
                    const char* base = Ap + (size_t)(arow + mt * 16) * (SPAD * 2) + kb * 2;
                    af[mt][0] = *(const uint32_t*)(base);
                    af[mt][1] = *(const uint32_t*)(base + 8 * (SPAD * 2));
                    af[mt][2] = *(const uint32_t*)(base + 16);
                    af[mt][3] = *(const uint32_t*)(base + 8 * (SPAD * 2) + 16);
                }
                uint32_t bf[4][2];
#pragma unroll
                for (int nt = 0; nt < 4; nt++) {
                    const char* base = Bp + (size_t)(brow + nt * 8) * (SPAD * 2) + kb * 2;
                    bf[nt][0] = *(const uint32_t*)(base);
                    bf[nt][1] = *(const uint32_t*)(base + 16);
                }
#pragma unroll
                for (int mt = 0; mt < 4; mt++)
#pragma unroll
                    for (int nt = 0; nt < 4; nt++)
                        mma_bf16(acc[mt][nt], af[mt][0], af[mt][1], af[mt][2], af[mt][3],
                                 bf[nt][0], bf[nt][1]);
            }
        }
        __syncthreads();
    }

    // epilogue
#pragma unroll
    for (int mt = 0; mt < 4; mt++) {
        const int gm = m0 + wm * 64 + mt * 16 + (lane >> 2);
#pragma unroll
        for (int nt = 0; nt < 4; nt++) {
            const int gn = n0 + wn * 32 + nt * 8 + (lane & 3) * 2;
            const float b0v = bias[gn], b1v = bias[gn + 1];
            float2 v0, v1;
            v0.x = epi_apply(acc[mt][nt][0] + b0v, EPI);
            v0.y = epi_apply(acc[mt][nt][1] + b1v, EPI);
            v1.x = epi_apply(acc[mt][nt][2] + b0v, EPI);
            v1.y = epi_apply(acc[mt][nt][3] + b1v, EPI);
            *reinterpret_cast<float2*>(C + (size_t)gm * N + gn)       = v0;
            *reinterpret_cast<float2*>(C + (size_t)(gm + 8) * N + gn) = v1;
        }
    }
}

// ======== fp32 -> (hi, lo) bf16 split ========
__global__ void split_k(const float* __restrict__ x, __nv_bfloat16* __restrict__ h,
                        __nv_bfloat16* __restrict__ l)
{
    size_t i = ((size_t)blockIdx.x * 256 + threadIdx.x) * 4;
    float4 v = *reinterpret_cast<const float4*>(x + i);
    float vv[4] = {v.x, v.y, v.z, v.w};
    __nv_bfloat16 hh[4], ll[4];
#pragma unroll
    for (int j = 0; j < 4; j++) {
        hh[j] = __float2bfloat16(vv[j]);
        ll[j] = __float2bfloat16(vv[j] - __bfloat162float(hh[j]));
    }
    *reinterpret_cast<__nv_bfloat162*>(h + i)     = __nv_bfloat162(hh[0], hh[1]);
    *reinterpret_cast<__nv_bfloat162*>(h + i + 2) = __nv_bfloat162(hh[2], hh[3]);
    *reinterpret_cast<__nv_bfloat162*>(l + i)     = __nv_bfloat162(ll[0], ll[1]);
    *reinterpret_cast<__nv_bfloat162*>(l + i + 2) = __nv_bfloat162(ll[2], ll[3]);
}

// ======== W[K,N] fp32 -> Wt[N,K] hi/lo bf16 (transpose + split) ========
__global__ void tsplit_k(const float* __restrict__ W, __nv_bfloat16* __restrict__ Th,
                         __nv_bfloat16* __restrict__ Tl, int K, int N)
{
    __shared__ float tile[32][33];
    int n0 = blockIdx.x * 32, k0 = blockIdx.y * 32;
    int tx = threadIdx.x, ty = threadIdx.y;   // 32 x 8
#pragma unroll
    for (int i = 0; i < 4; i++)
        tile[ty + 8 * i][tx] = W[(size_t)(k0 + ty + 8 * i) * N + n0 + tx];
    __syncthreads();
#pragma unroll
    for (int i = 0; i < 4; i++) {
        float v = tile[tx][ty + 8 * i];
        __nv_bfloat16 hi = __float2bfloat16(v);
        __nv_bfloat16 lo = __float2bfloat16(v - __bfloat162float(hi));
        size_t o = (size_t)(n0 + ty + 8 * i) * K + k0 + tx;
        Th[o] = hi;
        Tl[o] = lo;
    }
}

// ======== SIMT GEMMs for kv (TN, K=4096) and pq@kv (zscale, K=128) ========
#define BM 64
#define BN 64
#define BK 16

__global__ void __launch_bounds__(256) gemm_zscale_k(
    const float* __restrict__ A, const float* __restrict__ W,
    float* __restrict__ Cp, const float* __restrict__ zr,
    int M, int N, int K, long sA, long sW, long sC)
{
    __shared__ __align__(16) float As[BK][BM + 4];
    __shared__ __align__(16) float Bs[BK][BN + 4];

    int bz = blockIdx.z;
    A  += (long)bz * sA;
    W  += (long)bz * sW;
    Cp += (long)bz * sC;
    const float* zrow = zr + (long)bz * M;

    int m0 = blockIdx.y * BM;
    int n0 = blockIdx.x * BN;
    int tid = threadIdx.x;
    int tx = tid & 15, ty = tid >> 4;

    float acc[4][4] = {};

    for (int k0 = 0; k0 < K; k0 += BK) {
#pragma unroll
        for (int e = 0; e < 4; e++) {
            int idx = tid + e * 256;
            int r = idx >> 4, c = idx & 15;
            As[c][r] = A[(long)(m0 + r) * K + (k0 + c)];
        }
#pragma unroll
        for (int e = 0; e < 4; e++) {
            int idx = tid + e * 256;
            int r = idx >> 6, c = idx & 63;
            Bs[r][c] = W[(long)(k0 + r) * N + (n0 + c)];
        }
        __syncthreads();
#pragma unroll
        for (int kk = 0; kk < BK; kk++) {
            float4 av = *reinterpret_cast<const float4*>(&As[kk][ty * 4]);
            float4 bv = *reinterpret_cast<const float4*>(&Bs[kk][tx * 4]);
            float a4[4] = {av.x, av.y, av.z, av.w};
            float b4[4] = {bv.x, bv.y, bv.z, bv.w};
#pragma unroll
            for (int i = 0; i < 4; i++)
#pragma unroll
                for (int j = 0; j < 4; j++)
                    acc[i][j] = fmaf(a4[i], b4[j], acc[i][j]);
        }
        __syncthreads();
    }

#pragma unroll
    for (int i = 0; i < 4; i++) {
        int m = m0 + ty * 4 + i;
        float zs = 1.0f / (zrow[m] + 1e-6f);
#pragma unroll
        for (int j = 0; j < 4; j++)
            Cp[(long)m * N + (n0 + tx * 4 + j)] = acc[i][j] * zs;
    }
}

__global__ void __launch_bounds__(256) gemm_tn_k(
    const float* __restrict__ A, const float* __restrict__ Bp, float* __restrict__ Cp,
    int M, int N, int K, long sA, long sB, long sC)
{
    __shared__ __align__(16) float As[BK][BM + 4];
    __shared__ __align__(16) float Bs[BK][BN + 4];

    int bz = blockIdx.z;
    A  += (long)bz * sA;
    Bp += (long)bz * sB;
    Cp += (long)bz * sC;

    int m0 = blockIdx.y * BM;
    int n0 = blockIdx.x * BN;
    int tid = threadIdx.x;
    int tx = tid & 15, ty = tid >> 4;

    float acc[4][4] = {};

    for (int k0 = 0; k0 < K; k0 += BK) {
#pragma unroll
        for (int e = 0; e < 4; e++) {
            int idx = tid + e * 256;
            int r = idx >> 6, c = idx & 63;
            As[r][c] = A[(long)(k0 + r) * M + (m0 + c)];
            Bs[r][c] = Bp[(long)(k0 + r) * N + (n0 + c)];
        }
        __syncthreads();
#pragma unroll
        for (int kk = 0; kk < BK; kk++) {
            float4 av = *reinterpret_cast<const float4*>(&As[kk][ty * 4]);
            float4 bv = *reinterpret_cast<const float4*>(&Bs[kk][tx * 4]);
            float a4[4] = {av.x, av.y, av.z, av.w};
            float b4[4] = {bv.x, bv.y, bv.z, bv.w};
#pragma unroll
            for (int i = 0; i < 4; i++)
#pragma unroll
                for (int j = 0; j < 4; j++)
                    acc[i][j] = fmaf(a4[i], b4[j], acc[i][j]);
        }
        __syncthreads();
    }

#pragma unroll
    for (int i = 0; i < 4; i++) {
        int m = m0 + ty * 4 + i;
#pragma unroll
        for (int j = 0; j < 4; j++)
            Cp[(long)m * N + (n0 + tx * 4 + j)] = acc[i][j];
    }
}

// -------- embedding + positional --------
__global__ void embed_k(const int* __restrict__ x, const float* __restrict__ emb,
                        const float* __restrict__ pos, float* __restrict__ h)
{
    long idx = (long)blockIdx.x * 256 + threadIdx.x;
    int  d   = (int)(idx & (D_ - 1));
    long tok = idx >> 9;
    int  s   = (int)(tok & (S_ - 1));
    int  xv  = x[tok];
    h[idx] = emb[(long)xv * D_ + d] + pos[(long)s * D_ + d];
}

// -------- ksum[b,p] = sum_s pk[b,s,p] --------
__global__ void ksum_k(const float* __restrict__ pk, float* __restrict__ ks)
{
    int b = blockIdx.x;
    int tid = threadIdx.x;
    int p = tid & 127;
    int sg = tid >> 7;
    const float* base = pk + (long)b * S_ * P_;
    float s = 0.f;
    for (int si = sg; si < S_; si += 8)
        s += base[(long)si * P_ + p];
    __shared__ float red[1024];
    red[tid] = s;
    __syncthreads();
    if (sg == 0) {
        float t = 0.f;
#pragma unroll
        for (int g = 0; g < 8; g++) t += red[g * 128 + p];
        ks[b * P_ + p] = t;
    }
}

// -------- z[b,s] = pq[b,s,:] . ksum[b,:] --------
__global__ void z_k(const float* __restrict__ pq, const float* __restrict__ ks,
                    float* __restrict__ z)
{
    int row  = blockIdx.x * 8 + (threadIdx.x >> 5);
    int lane = threadIdx.x & 31;
    int b = row >> 12;
    const float* pr = pq + (long)row * P_;
    const float* kk = ks + b * P_;
    float s = 0.f;
#pragma unroll
    for (int i = lane; i < P_; i += 32) s += pr[i] * kk[i];
#pragma unroll
    for (int o = 16; o; o >>= 1) s += __shfl_xor_sync(0xffffffffu, s, o);
    if (!lane) z[row] = s;
}

// -------- layernorm over D=512 --------
__global__ void ln_k(const float* __restrict__ in, const float* __restrict__ g,
                     const float* __restrict__ bb, float* __restrict__ out)
{
    int row = blockIdx.x;
    int t = threadIdx.x;
    const float* x = in + (long)row * D_;
    float v0 = x[t], v1 = x[t + 256];

    float s = v0 + v1;
    __shared__ float red[8];
    __shared__ float red2[8];
#pragma unroll
    for (int o = 16; o; o >>= 1) s += __shfl_xor_sync(0xffffffffu, s, o);
    if ((t & 31) == 0) red[t >> 5] = s;
    __syncthreads();
    float tot = 0.f;
#pragma unroll
    for (int w = 0; w < 8; w++) tot += red[w];
    float mean = tot * (1.0f / 512.0f);

    float d0 = v0 - mean, d1 = v1 - mean;
    float q = d0 * d0 + d1 * d1;
#pragma unroll
    for (int o = 16; o; o >>= 1) q += __shfl_xor_sync(0xffffffffu, q, o);
    if ((t & 31) == 0) red2[t >> 5] = q;
    __syncthreads();
    float tq = 0.f;
#pragma unroll
    for (int w = 0; w < 8; w++) tq += red2[w];
    float inv = rsqrtf(tq * (1.0f / 512.0f) + 1e-5f);

    out[(long)row * D_ + t]       = d0 * inv * g[t] + bb[t];
    out[(long)row * D_ + t + 256] = d1 * inv * g[t + 256] + bb[t + 256];
}

// -------- mean pool over S --------
__global__ void pool_k(const float* __restrict__ h, float* __restrict__ pool)
{
    int b = blockIdx.x;
    int d = threadIdx.x;
    const float* base = h + (long)b * S_ * D_ + d;
    float s0 = 0.f, s1 = 0.f, s2 = 0.f, s3 = 0.f;
    for (int si = 0; si < S_; si += 4) {
        s0 += base[(long)(si + 0) * D_];
        s1 += base[(long)(si + 1) * D_];
        s2 += base[(long)(si + 2) * D_];
        s3 += base[(long)(si + 3) * D_];
    }
    pool[b * D_ + d] = (s0 + s1 + s2 + s3) * (1.0f / (float)S_);
}

// -------- head --------
__global__ void head1_k(const float* __restrict__ pool, const float* __restrict__ W,
                        const float* __restrict__ bias, float* __restrict__ h1)
{
    int b = blockIdx.x;
    int j = threadIdx.x;
    const float* p = pool + b * D_;
    float s = bias[j];
    for (int d = 0; d < D_; d++) s += p[d] * W[d * DH_ + j];
    h1[b * DH_ + j] = fmaxf(s, 0.f);
}

__global__ void head2_k(const float* __restrict__ h1, const float* __restrict__ W,
                        const float* __restrict__ bias, float* __restrict__ out)
{
    int i = threadIdx.x;
    int b = i / C_, c = i % C_;
    float s = bias[c];
    for (int d = 0; d < DH_; d++) s += h1[b * DH_ + d] * W[d * C_ + c];
    out[i] = s;
}

// -------- host orchestration --------
static float* sym_addr_f(const void* sym) {
    void* p = nullptr;
    cudaGetSymbolAddress(&p, sym);
    return (float*)p;
}
static __nv_bfloat16* sym_addr_b(const void* sym) {
    void* p = nullptr;
    cudaGetSymbolAddress(&p, sym);
    return (__nv_bfloat16*)p;
}

extern "C" void kernel_launch(void* const* d_in, const int* in_sizes, int n_in,
                              void* d_out, int out_size)
{
    const int*   x    = (const int*)d_in[0];
    const float* emb  = (const float*)d_in[1];
    const float* pos  = (const float*)d_in[2];
    const float* Wq   = (const float*)d_in[3];
    const float* bq   = (const float*)d_in[4];
    const float* Wk   = (const float*)d_in[5];
    const float* bk   = (const float*)d_in[6];
    const float* Wv   = (const float*)d_in[7];
    const float* bv   = (const float*)d_in[8];
    const float* Wf   = (const float*)d_in[9];
    const float* bf   = (const float*)d_in[10];
    const float* Wo   = (const float*)d_in[11];
    const float* bo   = (const float*)d_in[12];
    const float* lng  = (const float*)d_in[13];
    const float* lnb  = (const float*)d_in[14];
    const float* W1   = (const float*)d_in[15];
    const float* b1   = (const float*)d_in[16];
    const float* W2   = (const float*)d_in[17];
    const float* b2   = (const float*)d_in[18];
    const float* Wh1  = (const float*)d_in[19];
    const float* bh1  = (const float*)d_in[20];
    const float* Wh2  = (const float*)d_in[21];
    const float* bh2  = (const float*)d_in[22];
    float* out = (float*)d_out;

    float* h    = sym_addr_f(g_h);
    float* q    = sym_addr_f(g_q);
    float* k    = sym_addr_f(g_k);
    float* v    = sym_addr_f(g_v);
    float* a    = sym_addr_f(g_a);
    float* pq   = sym_addr_f(g_pq);
    float* pk   = sym_addr_f(g_pk);
    float* kv   = sym_addr_f(g_kv);
    float* ksum = sym_addr_f(g_ksum);
    float* z    = sym_addr_f(g_z);
    float* m    = sym_addr_f(g_m);
    float* pool = sym_addr_f(g_pool);
    float* h1   = sym_addr_f(g_h1);

    __nv_bfloat16* ah  = sym_addr_b(g_ah);
    __nv_bfloat16* al  = sym_addr_b(g_al);
    __nv_bfloat16* wth = sym_addr_b(g_wth);
    __nv_bfloat16* wtl = sym_addr_b(g_wtl);

    cudaFuncSetAttribute(gemm_mma<EP_NONE>, cudaFuncAttributeMaxDynamicSharedMemorySize, MMA_SMEM);
    cudaFuncSetAttribute(gemm_mma<EP_ELU1>, cudaFuncAttributeMaxDynamicSharedMemorySize, MMA_SMEM);
    cudaFuncSetAttribute(gemm_mma<EP_GELU>, cudaFuncAttributeMaxDynamicSharedMemorySize, MMA_SMEM);

    embed_k<<<(BS_ * D_) / 256, 256>>>(x, emb, pos, h);

    for (int l = 0; l < L_; l++) {
        const float* wq = Wq + (long)l * D_ * D_;
        const float* wk = Wk + (long)l * D_ * D_;
        const float* wv = Wv + (long)l * D_ * D_;
        const float* wf = Wf + (long)l * D_ * P_;
        const float* wo = Wo + (long)l * D_ * D_;
        const float* w1 = W1 + (long)l * D_ * DF_;
        const float* w2 = W2 + (long)l * DF_ * D_;

        dim3 tsD(32, 8);
        dim3 gMM_DD(D_ / 128, BS_ / 128);     // N=512
        dim3 gMM_DP(P_ / 128, BS_ / 128);     // N=128
        dim3 gMM_DF(DF_ / 128, BS_ / 128);    // N=2048

        // ---- QKV ----
        split_k<<<(BS_ * D_) / 1024, 256>>>(h, ah, al);
        tsplit_k<<<dim3(D_ / 32, D_ / 32), tsD>>>(wq, wth, wtl, D_, D_);
        gemm_mma<EP_NONE><<<gMM_DD, 256, MMA_SMEM>>>(ah, al, wth, wtl, bq + l * D_, q, BS_, D_, D_);
        tsplit_k<<<dim3(D_ / 32, D_ / 32), tsD>>>(wk, wth, wtl, D_, D_);
        gemm_mma<EP_NONE><<<gMM_DD, 256, MMA_SMEM>>>(ah, al, wth, wtl, bk + l * D_, k, BS_, D_, D_);
        tsplit_k<<<dim3(D_ / 32, D_ / 32), tsD>>>(wv, wth, wtl, D_, D_);
        gemm_mma<EP_NONE><<<gMM_DD, 256, MMA_SMEM>>>(ah, al, wth, wtl, bv + l * D_, v, BS_, D_, D_);

        // ---- feature maps ----
        tsplit_k<<<dim3(P_ / 32, D_ / 32), tsD>>>(wf, wth, wtl, D_, P_);
        split_k<<<(BS_ * D_) / 1024, 256>>>(q, ah, al);
        gemm_mma<EP_ELU1><<<gMM_DP, 256, MMA_SMEM>>>(ah, al, wth, wtl, bf + l * P_, pq, BS_, P_, D_);
        split_k<<<(BS_ * D_) / 1024, 256>>>(k, ah, al);
        gemm_mma<EP_ELU1><<<gMM_DP, 256, MMA_SMEM>>>(ah, al, wth, wtl, bf + l * P_, pk, BS_, P_, D_);

        // ---- linear attention core (SIMT fp32) ----
        ksum_k<<<B_, 1024>>>(pk, ksum);
        dim3 gKV(D_ / BN, P_ / BM, B_);
        gemm_tn_k<<<gKV, 256>>>(pk, v, kv, P_, D_, S_,
                                (long)S_ * P_, (long)S_ * D_, (long)P_ * D_);
        z_k<<<BS_ / 8, 256>>>(pq, ksum, z);
        dim3 gAV(D_ / BN, S_ / BM, B_);
        gemm_zscale_k<<<gAV, 256>>>(pq, kv, q, z, S_, D_, P_,
                                    (long)S_ * P_, (long)P_ * D_, (long)S_ * D_);

        // ---- Wo ----
        split_k<<<(BS_ * D_) / 1024, 256>>>(q, ah, al);
        tsplit_k<<<dim3(D_ / 32, D_ / 32), tsD>>>(wo, wth, wtl, D_, D_);
        gemm_mma<EP_NONE><<<gMM_DD, 256, MMA_SMEM>>>(ah, al, wth, wtl, bo + l * D_, a, BS_, D_, D_);

        ln_k<<<BS_, 256>>>(a, lng + l * D_, lnb + l * D_, a);

        // ---- MLP ----
        split_k<<<(BS_ * D_) / 1024, 256>>>(a, ah, al);
        tsplit_k<<<dim3(DF_ / 32, D_ / 32), tsD>>>(w1, wth, wtl, D_, DF_);
        gemm_mma<EP_GELU><<<gMM_DF, 256, MMA_SMEM>>>(ah, al, wth, wtl, b1 + l * DF_, m, BS_, DF_, D_);
        split_k<<<(BS_ * DF_) / 1024, 256>>>(m, ah, al);
        tsplit_k<<<dim3(D_ / 32, DF_ / 32), tsD>>>(w2, wth, wtl, DF_, D_);
        gemm_mma<EP_NONE><<<gMM_DD, 256, MMA_SMEM>>>(ah, al, wth, wtl, b2 + l * D_, h, BS_, D_, DF_);
    }

    pool_k<<<B_, 512>>>(h, pool);
    head1_k<<<B_, DH_>>>(pool, Wh1, bh1, h1);
    head2_k<<<1, B_ * C_>>>(h1, Wh2, bh2, out);
}